// round 13
// baseline (speedup 1.0000x reference)
#include <cuda_runtime.h>
#include <math.h>
#include <stdint.h>

#define BQ 2048
#define NQ 128
#define HQ 512
#define TAUC 0.05f
#define BT 8
#define KC 32
#define NITER 4    // Richardson iterations (even); 5 apps already at fp32 floor

// padded index: 32-float groups padded to 36 words -> banks (4g + i) % 32
#define PX(i) ((((i) >> 5) * 36) + ((i) & 31))

// packed fp32x2 FMA (Blackwell, PTX-only)
#define FMA_X2(acc, a, b) \
    asm("fma.rn.f32x2 %0, %1, %2, %3;" : "=l"(acc) : "l"(a), "l"(b), "l"(acc))

// scratch (allocation-free rule: __device__ globals)
__device__ float g_q[BQ * NQ];
__device__ float g_p[BQ * NQ];
__device__ float g_o[BQ * NQ];

// ---------------------------------------------------------------------------
// Kernel A: tiled GEMM, packed f32x2 FMA. CTA = 8 batches x 128 n, one weight
// (blockIdx.y). W staged via smem (pad-36, STS.128/LDS.128 conflict-free)
// with register-prefetch double buffering.
// ---------------------------------------------------------------------------
__global__ void __launch_bounds__(256) gemm_act_kernel(
    const float* __restrict__ hidden,
    const float* __restrict__ Wq, const float* __restrict__ Wp,
    const float* __restrict__ Wo,
    const float* __restrict__ bq, const float* __restrict__ bp,
    const float* __restrict__ bo)
{
    __shared__ float Ht[BT][HQ];        // 16 KB
    __shared__ float Wt[NQ][36];        // 18 KB, pad 36 -> conflict-free 128b

    const int tid = threadIdx.x;
    const int b0 = blockIdx.x * BT;
    const int w  = blockIdx.y;

    const float* W    = (w == 0) ? Wq : (w == 1) ? Wp : Wo;
    const float* bias = (w == 0) ? bq : (w == 1) ? bp : bo;
    float* gout       = (w == 0) ? g_q : (w == 1) ? g_p : g_o;

    // load hidden tile (coalesced float4)
    {
        const float4* hg = (const float4*)(hidden + (size_t)b0 * HQ);
        float4* hs = (float4*)&Ht[0][0];
#pragma unroll
        for (int i = 0; i < (BT * HQ / 4) / 256; i++)
            hs[tid + 256 * i] = hg[tid + 256 * i];
    }

    const int n    = tid & 127;
    const int kh   = tid >> 7;
    const int wrp  = tid >> 5;
    const int lane = tid & 31;
    const int rowsub = lane >> 3;      // 4 rows per warp per instr
    const int f4     = lane & 7;       // 8 float4 per 32-float chunk row
    const float4* W4 = (const float4*)W;

    int srow[4];
#pragma unroll
    for (int i = 0; i < 4; i++) srow[i] = wrp * 16 + i * 4 + rowsub;

    float4 v[4];
#pragma unroll
    for (int i = 0; i < 4; i++)
        v[i] = W4[(size_t)srow[i] * (HQ / 4) + f4];   // prefetch chunk 0

    uint64_t acc2[8] = {0ull, 0ull, 0ull, 0ull, 0ull, 0ull, 0ull, 0ull};

#pragma unroll 1
    for (int c = 0; c < HQ / KC; c++) {
        __syncthreads();
#pragma unroll
        for (int i = 0; i < 4; i++)
            *(float4*)&Wt[srow[i]][f4 * 4] = v[i];    // STS.128, conflict-free
        __syncthreads();

        if (c + 1 < HQ / KC) {                        // prefetch chunk c+1
#pragma unroll
            for (int i = 0; i < 4; i++)
                v[i] = W4[(size_t)srow[i] * (HQ / 4) + (c + 1) * (KC / 4) + f4];
        }

        const int k0 = c * KC;
#pragma unroll
        for (int j = 0; j < 4; j++) {
            const int kk = kh * 16 + j * 4;
            const ulonglong2 wv = *(const ulonglong2*)&Wt[n][kk]; // (w0,w1),(w2,w3)
#pragma unroll
            for (int m = 0; m < 8; m++) {
                const ulonglong2 hp = *(const ulonglong2*)&Ht[m][k0 + kk];
                FMA_X2(acc2[m], hp.x, wv.x);
                FMA_X2(acc2[m], hp.y, wv.y);
            }
        }
    }

    // combine the two k-halves via smem (reuse Wt as scratch)
    __syncthreads();
    float* red = &Wt[0][0];
    if (kh == 1) {
#pragma unroll
        for (int m = 0; m < 8; m++) {
            const float2 a = *(const float2*)&acc2[m];
            red[n * 8 + m] = a.x + a.y;
        }
    }
    __syncthreads();
    if (kh == 0) {
        const float bv = bias[n];
#pragma unroll
        for (int m = 0; m < 8; m++) {
            const float2 a = *(const float2*)&acc2[m];
            const float l = a.x + a.y + red[n * 8 + m] + bv;
            float vv;
            if (w == 0) {
                vv = tanhf(l);                                         // q
            } else if (w == 1) {
                vv = 1.0f / (1.0f + expf(-l));                         // p
            } else {
                vv = fmaxf(l, 0.0f) + log1pf(expf(-fabsf(l))) + 1e-6f; // omega
            }
            gout[(size_t)(b0 + m) * NQ + n] = vv;
        }
    }
}

// ---------------------------------------------------------------------------
// Kernel B: per-batch solve of (I + M D) mu = pi + M t via Richardson.
// 512 threads: thread (r = tid>>2, h = tid&3) owns E[r][h*32..+31] in regs.
// sigma loaded IN-PLACE into E regs (8 back-to-back LDG.128, MLP=8), then
// transformed. x in smem with 36-word padding -> conflict-free LDS.128.
// ---------------------------------------------------------------------------
__device__ __forceinline__ float matvec_quarter(const float4* __restrict__ e4,
                                                const float* __restrict__ xbase,
                                                int h)
{
    const float4* x4 = (const float4*)xbase + h * 9;   // 36 words = 9 float4
    float a0 = 0.f, a1 = 0.f, a2 = 0.f, a3 = 0.f;
#pragma unroll
    for (int k = 0; k < 8; k++) {
        const float4 xv = x4[k];
        a0 = fmaf(e4[k].x, xv.x, a0);
        a1 = fmaf(e4[k].y, xv.y, a1);
        a2 = fmaf(e4[k].z, xv.z, a2);
        a3 = fmaf(e4[k].w, xv.w, a3);
    }
    float sum = (a0 + a1) + (a2 + a3);
    sum += __shfl_xor_sync(0xffffffffu, sum, 1);
    sum += __shfl_xor_sync(0xffffffffu, sum, 2);
    return sum;
}

__global__ void __launch_bounds__(512, 2) solve_kernel(
    const float* __restrict__ pi,
    const float* __restrict__ sigma,
    float* __restrict__ out)
{
    __shared__ __align__(16) float sm_d[144];
    __shared__ __align__(16) float sm_u[144];
    __shared__ __align__(16) float xA[144];
    __shared__ __align__(16) float xB[144];
    __shared__ __align__(16) float sm_a[NQ];

    const int tid = threadIdx.x;
    const int b = blockIdx.x;
    const int r = tid >> 2;
    const int h = tid & 3;

    // Load sigma rows RAW into E registers first: 8 independent LDG.128,
    // no transform in between -> full MLP, ~2x effective HBM bandwidth.
    float4 e4[8];
    const float4* sg = (const float4*)(sigma + (size_t)b * NQ * NQ) + r * 32 + h * 8;
#pragma unroll
    for (int k = 0; k < 8; k++) e4[k] = sg[k];

    if (tid < NQ) {
        const float q  = g_q[b * NQ + tid];
        const float p  = g_p[b * NQ + tid];
        const float om = g_o[b * NQ + tid];
        const float d  = p * p / om + 1e-6f;
        sm_d[PX(tid)] = d;
        sm_u[PX(tid)] = (p * q / om) / d;
        sm_a[tid] = pi[b * NQ + tid];
    }
    __syncthreads();

    // Transform in place: E = (TAU*sigma + 1e-6 I) * diag(d)
    const float4* d4 = (const float4*)sm_d + h * 9;
#pragma unroll
    for (int k = 0; k < 8; k++) {
        const float4 dv = d4[k];
        const int j = h * 32 + 4 * k;
        e4[k].x = (TAUC * e4[k].x + ((r == j + 0) ? 1e-6f : 0.f)) * dv.x;
        e4[k].y = (TAUC * e4[k].y + ((r == j + 1) ? 1e-6f : 0.f)) * dv.y;
        e4[k].z = (TAUC * e4[k].z + ((r == j + 2) ? 1e-6f : 0.f)) * dv.z;
        e4[k].w = (TAUC * e4[k].w + ((r == j + 3) ? 1e-6f : 0.f)) * dv.w;
    }

    // a = pi + M t = pi + E * (t./d);  x0 = a
    {
        const float s = matvec_quarter(e4, sm_u, h);
        if (h == 0) {
            const float a = sm_a[r] + s;
            sm_a[r] = a;
            xA[PX(r)] = a;
        }
    }
    __syncthreads();

    // Richardson: x <- a - E x   (converges to (I + E)^{-1} a)
#pragma unroll 1
    for (int it = 0; it < NITER / 2; it++) {
        float s = matvec_quarter(e4, xA, h);
        if (h == 0) xB[PX(r)] = sm_a[r] - s;
        __syncthreads();
        s = matvec_quarter(e4, xB, h);
        if (h == 0) xA[PX(r)] = sm_a[r] - s;
        __syncthreads();
    }

    if (tid < NQ) out[b * NQ + tid] = xA[PX(tid)];
}

// ---------------------------------------------------------------------------
extern "C" void kernel_launch(void* const* d_in, const int* in_sizes, int n_in,
                              void* d_out, int out_size)
{
    const float* hidden = (const float*)d_in[0];
    const float* pi     = (const float*)d_in[1];
    const float* sigma  = (const float*)d_in[2];
    const float* Wq     = (const float*)d_in[3];
    const float* bq     = (const float*)d_in[4];
    const float* Wp     = (const float*)d_in[5];
    const float* bp     = (const float*)d_in[6];
    const float* Wo     = (const float*)d_in[7];
    const float* bo     = (const float*)d_in[8];

    dim3 gridA(BQ / BT, 3, 1);
    gemm_act_kernel<<<gridA, 256>>>(hidden, Wq, Wp, Wo, bq, bp, bo);
    solve_kernel<<<BQ, 512>>>(pi, sigma, (float*)d_out);
}

// round 14
// speedup vs baseline: 1.2187x; 1.2187x over previous
#include <cuda_runtime.h>
#include <math.h>
#include <stdint.h>

#define BQ 2048
#define NQ 128
#define HQ 512
#define TAUC 0.05f
#define BT 8
#define KC 32
#define NITER 4    // Richardson iterations (even); 5 apps = fp32 floor
#define SGRID 296  // persistent solve CTAs (2 per SM)

// padded index: 32-float groups padded to 36 words -> banks (4g + i) % 32
#define PX(i) ((((i) >> 5) * 36) + ((i) & 31))

// sigma smem layout: row r, slice h (32 floats) at 144*r + 36*h (+4k)
#define SIG_WORDS (NQ * 144)              // 18432 floats = 72 KB
#define SOLVE_SMEM_FLOATS (SIG_WORDS + 4 * 144 + NQ)
#define SOLVE_SMEM_BYTES (SOLVE_SMEM_FLOATS * 4)

// scratch (allocation-free rule: __device__ globals)
__device__ float g_q[BQ * NQ];
__device__ float g_p[BQ * NQ];
__device__ float g_o[BQ * NQ];

// ---------------------------------------------------------------------------
// Kernel A: tiled GEMM (R12 known-good). CTA = 8 batches x 128 n, one weight
// (blockIdx.y). W staged via smem with register-prefetch double buffering.
// ---------------------------------------------------------------------------
__global__ void __launch_bounds__(256) gemm_act_kernel(
    const float* __restrict__ hidden,
    const float* __restrict__ Wq, const float* __restrict__ Wp,
    const float* __restrict__ Wo,
    const float* __restrict__ bq, const float* __restrict__ bp,
    const float* __restrict__ bo)
{
    __shared__ float Ht[BT][HQ];        // 16 KB
    __shared__ float Wt[NQ][KC + 1];    // 16.5 KB, pad 33 -> bank (n+kk)%32

    const int tid = threadIdx.x;
    const int b0 = blockIdx.x * BT;
    const int w  = blockIdx.y;

    const float* W    = (w == 0) ? Wq : (w == 1) ? Wp : Wo;
    const float* bias = (w == 0) ? bq : (w == 1) ? bp : bo;
    float* gout       = (w == 0) ? g_q : (w == 1) ? g_p : g_o;

    {
        const float4* hg = (const float4*)(hidden + (size_t)b0 * HQ);
        float4* hs = (float4*)&Ht[0][0];
#pragma unroll
        for (int i = 0; i < (BT * HQ / 4) / 256; i++)
            hs[tid + 256 * i] = hg[tid + 256 * i];
    }

    const int n    = tid & 127;
    const int kh   = tid >> 7;
    const int wrp  = tid >> 5;
    const int lane = tid & 31;
    const int rowsub = lane >> 3;
    const int f4     = lane & 7;
    const float4* W4 = (const float4*)W;

    int srow[4];
#pragma unroll
    for (int i = 0; i < 4; i++) srow[i] = wrp * 16 + i * 4 + rowsub;

    float4 v[4];
#pragma unroll
    for (int i = 0; i < 4; i++)
        v[i] = W4[(size_t)srow[i] * (HQ / 4) + f4];   // prefetch chunk 0

    float acc[8] = {0.f, 0.f, 0.f, 0.f, 0.f, 0.f, 0.f, 0.f};

#pragma unroll 1
    for (int c = 0; c < HQ / KC; c++) {
        __syncthreads();
#pragma unroll
        for (int i = 0; i < 4; i++) {
            Wt[srow[i]][f4 * 4 + 0] = v[i].x;
            Wt[srow[i]][f4 * 4 + 1] = v[i].y;
            Wt[srow[i]][f4 * 4 + 2] = v[i].z;
            Wt[srow[i]][f4 * 4 + 3] = v[i].w;
        }
        __syncthreads();

        if (c + 1 < HQ / KC) {
#pragma unroll
            for (int i = 0; i < 4; i++)
                v[i] = W4[(size_t)srow[i] * (HQ / 4) + (c + 1) * (KC / 4) + f4];
        }

        const int k0 = c * KC;
#pragma unroll
        for (int j = 0; j < 4; j++) {
            const int kk = kh * 16 + j * 4;
            const float w0 = Wt[n][kk + 0];
            const float w1 = Wt[n][kk + 1];
            const float w2 = Wt[n][kk + 2];
            const float w3 = Wt[n][kk + 3];
#pragma unroll
            for (int m = 0; m < 8; m++) {
                const float4 hv = *(const float4*)&Ht[m][k0 + kk];
                acc[m] = fmaf(hv.x, w0, fmaf(hv.y, w1,
                         fmaf(hv.z, w2, fmaf(hv.w, w3, acc[m]))));
            }
        }
    }

    __syncthreads();
    float* red = &Wt[0][0];
    if (kh == 1) {
#pragma unroll
        for (int m = 0; m < 8; m++) red[n * 8 + m] = acc[m];
    }
    __syncthreads();
    if (kh == 0) {
        const float bv = bias[n];
#pragma unroll
        for (int m = 0; m < 8; m++) {
            const float l = acc[m] + red[n * 8 + m] + bv;
            float vv;
            if (w == 0) {
                vv = tanhf(l);                                         // q
            } else if (w == 1) {
                vv = 1.0f / (1.0f + expf(-l));                         // p
            } else {
                vv = fmaxf(l, 0.0f) + log1pf(expf(-fabsf(l))) + 1e-6f; // omega
            }
            gout[(size_t)(b0 + m) * NQ + n] = vv;
        }
    }
}

// ---------------------------------------------------------------------------
// Kernel B: persistent pipelined solve. Each CTA handles batches
// b, b+SGRID, ... For batch i: E in registers; while Richardson runs,
// sigma(i+1) streams into the (now free) smem buffer via cp.async.
// ---------------------------------------------------------------------------
__device__ __forceinline__ void cp16(uint32_t dst, const void* src)
{
    asm volatile("cp.async.cg.shared.global [%0], [%1], 16;"
                 :: "r"(dst), "l"(src));
}

// stage one batch's sigma (64 KB) into padded smem layout; 8 chunks/thread
__device__ __forceinline__ void prefetch_sigma(uint32_t sig_base,
                                               const float* __restrict__ sigma,
                                               int b, int tid)
{
    const char* src = (const char*)(sigma + (size_t)b * NQ * NQ);
#pragma unroll
    for (int j = 0; j < 8; j++) {
        const int c   = tid + 512 * j;        // 16B chunk id, 0..4095
        const int row = c >> 5;               // one row per warp per j
        const int g   = c & 31;
        const uint32_t dst = sig_base +
            4u * (144 * row + 36 * (g >> 3) + 4 * (g & 7));
        cp16(dst, src + 16 * (size_t)c);
    }
}

__device__ __forceinline__ float matvec_quarter(const float4* __restrict__ e4,
                                                const float* __restrict__ xbase,
                                                int h)
{
    const float4* x4 = (const float4*)xbase + h * 9;   // 36 words = 9 float4
    float a0 = 0.f, a1 = 0.f, a2 = 0.f, a3 = 0.f;
#pragma unroll
    for (int k = 0; k < 8; k++) {
        const float4 xv = x4[k];
        a0 = fmaf(e4[k].x, xv.x, a0);
        a1 = fmaf(e4[k].y, xv.y, a1);
        a2 = fmaf(e4[k].z, xv.z, a2);
        a3 = fmaf(e4[k].w, xv.w, a3);
    }
    float sum = (a0 + a1) + (a2 + a3);
    sum += __shfl_xor_sync(0xffffffffu, sum, 1);
    sum += __shfl_xor_sync(0xffffffffu, sum, 2);
    return sum;
}

__global__ void __launch_bounds__(512, 2) solve_kernel(
    const float* __restrict__ pi,
    const float* __restrict__ sigma,
    float* __restrict__ out)
{
    extern __shared__ float sm[];
    float* sig  = sm;                       // 18432 floats (padded sigma)
    float* sm_d = sm + SIG_WORDS;           // 144
    float* sm_u = sm_d + 144;               // 144
    float* xA   = sm_u + 144;               // 144
    float* xB   = xA + 144;                 // 144
    float* sm_a = xB + 144;                 // 128

    const int tid = threadIdx.x;
    const int r = tid >> 2;
    const int h = tid & 3;
    const uint32_t sig_base = (uint32_t)__cvta_generic_to_shared(sig);

    int b = blockIdx.x;
    prefetch_sigma(sig_base, sigma, b, tid);
    asm volatile("cp.async.commit_group;");

#pragma unroll 1
    for (; b < BQ; b += SGRID) {
        // aux for this batch (L2-resident from kernel A)
        if (tid < NQ) {
            const float q  = g_q[b * NQ + tid];
            const float p  = g_p[b * NQ + tid];
            const float om = g_o[b * NQ + tid];
            const float d  = p * p / om + 1e-6f;
            sm_d[PX(tid)] = d;
            sm_u[PX(tid)] = (p * q / om) / d;
            sm_a[tid] = pi[b * NQ + tid];
        }
        asm volatile("cp.async.wait_group 0;" ::: "memory");
        __syncthreads();

        // transform sigma(smem) -> E regs: E = (TAU*sig + 1e-6 I) * diag(d)
        float4 e4[8];
        {
            const float4* srow = (const float4*)(sig + 144 * r + 36 * h);
            const float4* d4 = (const float4*)sm_d + h * 9;
#pragma unroll
            for (int k = 0; k < 8; k++) {
                float4 s = srow[k];
                const float4 dv = d4[k];
                const int j = h * 32 + 4 * k;
                s.x = (TAUC * s.x + ((r == j + 0) ? 1e-6f : 0.f)) * dv.x;
                s.y = (TAUC * s.y + ((r == j + 1) ? 1e-6f : 0.f)) * dv.y;
                s.z = (TAUC * s.z + ((r == j + 2) ? 1e-6f : 0.f)) * dv.z;
                s.w = (TAUC * s.w + ((r == j + 3) ? 1e-6f : 0.f)) * dv.w;
                e4[k] = s;
            }
        }
        __syncthreads();   // all threads done reading sig -> buffer reusable

        // start streaming next batch's sigma NOW; Richardson below hides it
        if (b + SGRID < BQ)
            prefetch_sigma(sig_base, sigma, b + SGRID, tid);
        asm volatile("cp.async.commit_group;");

        // a = pi + M t = pi + E * (t./d);  x0 = a
        {
            const float s = matvec_quarter(e4, sm_u, h);
            if (h == 0) {
                const float a = sm_a[r] + s;
                sm_a[r] = a;
                xA[PX(r)] = a;
            }
        }
        __syncthreads();

        // Richardson: x <- a - E x
#pragma unroll 1
        for (int it = 0; it < NITER / 2; it++) {
            float s = matvec_quarter(e4, xA, h);
            if (h == 0) xB[PX(r)] = sm_a[r] - s;
            __syncthreads();
            s = matvec_quarter(e4, xB, h);
            if (h == 0) xA[PX(r)] = sm_a[r] - s;
            __syncthreads();
        }

        if (tid < NQ) out[b * NQ + tid] = xA[PX(tid)];
        __syncthreads();   // protect aux/xA before next iteration overwrites
    }
}

// ---------------------------------------------------------------------------
extern "C" void kernel_launch(void* const* d_in, const int* in_sizes, int n_in,
                              void* d_out, int out_size)
{
    const float* hidden = (const float*)d_in[0];
    const float* pi     = (const float*)d_in[1];
    const float* sigma  = (const float*)d_in[2];
    const float* Wq     = (const float*)d_in[3];
    const float* bq     = (const float*)d_in[4];
    const float* Wp     = (const float*)d_in[5];
    const float* bp     = (const float*)d_in[6];
    const float* Wo     = (const float*)d_in[7];
    const float* bo     = (const float*)d_in[8];

    // idempotent, deterministic; needed for 74.8 KB dynamic smem
    cudaFuncSetAttribute(solve_kernel,
                         cudaFuncAttributeMaxDynamicSharedMemorySize,
                         SOLVE_SMEM_BYTES);

    dim3 gridA(BQ / BT, 3, 1);
    gemm_act_kernel<<<gridA, 256>>>(hidden, Wq, Wp, Wo, bq, bp, bo);
    solve_kernel<<<SGRID, 512, SOLVE_SMEM_BYTES>>>(pi, sigma, (float*)d_out);
}